// round 14
// baseline (speedup 1.0000x reference)
#include <cuda_runtime.h>
#include <math.h>

#define AS 132  // padded activation row stride (floats)

// ================= global scratch =================
__device__ float  g_branch[4096 * 128];   // branch MLP output per (b,o)
__device__ int    g_nact;                 // dist-active row counter
__device__ int    g_njoint;               // joint-active row counter
__device__ int    g_tile;                 // trunk dynamic tile counter
__device__ int    g_cidx[262144];         // compacted dist-active row index
__device__ float  g_cin[262144 * 12];     // compacted trunk inputs
__device__ int    g_jidx[262144];         // compacted joint row index
__device__ float  g_jin[262144 * 16];     // compacted joint inputs (15 used)
__device__ float2 g_isc[4096];            // (cos,sin) of init angle per (b,o)
__device__ float2 g_qsc[4096];            // (cos,sin) of query angle per (b,t)

// ================= branch kernel layout (256 thr) =================
#define BO_W    0
#define BO_A    16384
#define BO_BW0  (BO_A + 64*AS)
#define BO_BB0  (BO_BW0 + 640)
#define BO_BBS0 (BO_BB0 + 128)
#define BO_BBS1 (BO_BBS0 + 128)
#define BO_IN   (BO_BBS1 + 128)
#define SM_BR_FLOATS (BO_IN + 64*8)
#define SM_BR_BYTES  (SM_BR_FLOATS * 4)

// ======== trunk kernel layout (256 thr, 64-row tile, 2 CTA/SM, 16 warps/SM) ====
#define T_W    0                       // 128x128 current-layer weights (16384)
#define T_A    16384                   // 64 x AS activations (8448)
#define T_TW0  (T_A + 64*AS)           // trunk_w0 9x128 (1152)
#define T_TB0  (T_TW0 + 1152)
#define T_TBS0 (T_TB0 + 128)
#define T_TBS1 (T_TBS0 + 128)
#define T_OW   (T_TBS1 + 128)          // 384
#define T_OB   (T_OW + 384)            // 4
#define T_IN   (T_OB + 4)              // 64x12 = 768
#define T_IDX  (T_IN + 768)            // 64
#define T_FLOATS (T_IDX + 64)
#define T_BYTES  (T_FLOATS * 4)        // 110352 B -> 2 CTAs/SM

// ================= helpers =================
__device__ __forceinline__ float ptseg(float px, float py, float ax, float ay,
                                       float abx, float aby, float s) {
    float t = ((px - ax) * abx + (py - ay) * aby) / s;
    t = fminf(fmaxf(t, 0.f), 1.f);
    float dx = px - (ax + t * abx);
    float dy = py - (ay + t * aby);
    return sqrtf(dx * dx + dy * dy);
}

// ---- 4x8 micro-tile GEMM ----
__device__ __forceinline__ void gemm128(const float* __restrict__ sA,
                                        const float* __restrict__ sW,
                                        int row0, int col0, float acc[4][8]) {
#pragma unroll 2
    for (int k = 0; k < 128; k += 4) {
        float a[4][4];
#pragma unroll
        for (int r = 0; r < 4; r++) {
            float4 t = *reinterpret_cast<const float4*>(sA + (row0 + r) * AS + k);
            a[r][0] = t.x; a[r][1] = t.y; a[r][2] = t.z; a[r][3] = t.w;
        }
#pragma unroll
        for (int kk = 0; kk < 4; kk++) {
            float4 t0 = *reinterpret_cast<const float4*>(sW + (k + kk) * 128 + col0);
            float4 t1 = *reinterpret_cast<const float4*>(sW + (k + kk) * 128 + col0 + 4);
            float bv[8] = {t0.x, t0.y, t0.z, t0.w, t1.x, t1.y, t1.z, t1.w};
#pragma unroll
            for (int r = 0; r < 4; r++)
#pragma unroll
                for (int c = 0; c < 8; c++)
                    acc[r][c] = fmaf(a[r][kk], bv[c], acc[r][c]);
        }
    }
}

template <int K, int STRIDE>
__device__ __forceinline__ void gemm_small(const float* __restrict__ sIn,
                                           const float* __restrict__ sW0,
                                           int row0, int col0, float acc[4][8]) {
#pragma unroll
    for (int k = 0; k < K; k++) {
        float a[4];
#pragma unroll
        for (int r = 0; r < 4; r++) a[r] = sIn[(row0 + r) * STRIDE + k];
        float4 t0 = *reinterpret_cast<const float4*>(sW0 + k * 128 + col0);
        float4 t1 = *reinterpret_cast<const float4*>(sW0 + k * 128 + col0 + 4);
        float bv[8] = {t0.x, t0.y, t0.z, t0.w, t1.x, t1.y, t1.z, t1.w};
#pragma unroll
        for (int r = 0; r < 4; r++)
#pragma unroll
            for (int c = 0; c < 8; c++)
                acc[r][c] = fmaf(a[r], bv[c], acc[r][c]);
    }
}

__device__ __forceinline__ void store_relu(float* sA, int row0, int col0,
                                           const float acc[4][8]) {
#pragma unroll
    for (int r = 0; r < 4; r++) {
        float4 v0 = make_float4(fmaxf(acc[r][0], 0.f), fmaxf(acc[r][1], 0.f),
                                fmaxf(acc[r][2], 0.f), fmaxf(acc[r][3], 0.f));
        float4 v1 = make_float4(fmaxf(acc[r][4], 0.f), fmaxf(acc[r][5], 0.f),
                                fmaxf(acc[r][6], 0.f), fmaxf(acc[r][7], 0.f));
        *reinterpret_cast<float4*>(sA + (row0 + r) * AS + col0)     = v0;
        *reinterpret_cast<float4*>(sA + (row0 + r) * AS + col0 + 4) = v1;
    }
}

__device__ __forceinline__ void init_acc(const float* __restrict__ bias,
                                         int col0, float acc[4][8]) {
#pragma unroll
    for (int c = 0; c < 8; c++) {
        float bv = bias[col0 + c];
#pragma unroll
        for (int r = 0; r < 4; r++) acc[r][c] = bv;
    }
}

// ================= kernel: sincos dedup + counter zeroing =================
__global__ void __launch_bounds__(128)
sincos_kernel(const float* __restrict__ init_x, const float* __restrict__ query_x) {
    int i = blockIdx.x * 128 + threadIdx.x;
    if (i == 0) { g_nact = 0; g_njoint = 0; g_tile = 0; }
    if (i < 4096) {
        double s, c;
        sincos((double)init_x[(size_t)i * 9 + 3] * 100.0, &s, &c);
        g_isc[i] = make_float2((float)c, (float)s);
    } else if (i < 8192) {
        int q = i - 4096;
        double s, c;
        sincos((double)query_x[(size_t)q * 9 + 3] * 100.0, &s, &c);
        g_qsc[q] = make_float2((float)c, (float)s);
    }
}

// ================= branch prepass (4096 rows) =================
__global__ void __launch_bounds__(256, 1)
branch_kernel(const float* __restrict__ init_x,
              const float* __restrict__ branch_w0, const float* __restrict__ branch_b0,
              const float* __restrict__ branch_ws, const float* __restrict__ branch_bs) {
    extern __shared__ float sm[];
    const int tid = threadIdx.x;
    const int tx = tid & 15, ty = tid >> 4;
    const int row0 = ty * 4, col0 = tx * 8;

    float* sW   = sm + BO_W;
    float* sA   = sm + BO_A;
    float* sBw0 = sm + BO_BW0;
    float* sBb0 = sm + BO_BB0;
    float* sBbs0= sm + BO_BBS0;
    float* sBbs1= sm + BO_BBS1;
    float* sIn  = sm + BO_IN;

    for (int i = tid; i < 640; i += 256) sBw0[i] = branch_w0[i];
    if (tid < 128) {
        sBb0[tid]  = branch_b0[tid];
        sBbs0[tid] = branch_bs[tid];
        sBbs1[tid] = branch_bs[128 + tid];
    }

    if (tid < 64) {
        int bo = blockIdx.x * 64 + tid;
        const float* ip = init_x + (size_t)bo * 9;
        float* in = sIn + tid * 8;
        in[0] = 0.f; in[1] = 0.f; in[2] = ip[2]; in[3] = ip[3]; in[4] = ip[4];
        in[5] = 0.f; in[6] = 0.f; in[7] = 0.f;
    } else {
        const float4* src = reinterpret_cast<const float4*>(branch_ws);
        float4* dst = reinterpret_cast<float4*>(sW);
        for (int i = tid - 64; i < 4096; i += 192) dst[i] = src[i];
    }
    __syncthreads();

    float acc[4][8];
    init_acc(sBb0, col0, acc);
    gemm_small<5, 8>(sIn, sBw0, row0, col0, acc);
    store_relu(sA, row0, col0, acc);
    __syncthreads();

    init_acc(sBbs0, col0, acc);
    gemm128(sA, sW, row0, col0, acc);
    __syncthreads();
    store_relu(sA, row0, col0, acc);
    {
        const float4* src = reinterpret_cast<const float4*>(branch_ws + 128 * 128);
        float4* dst = reinterpret_cast<float4*>(sW);
        for (int i = tid; i < 4096; i += 256) dst[i] = src[i];
    }
    __syncthreads();

    init_acc(sBbs1, col0, acc);
    gemm128(sA, sW, row0, col0, acc);

#pragma unroll
    for (int r = 0; r < 4; r++) {
        int m = blockIdx.x * 64 + row0 + r;
        *reinterpret_cast<float4*>(&g_branch[m * 128 + col0]) =
            make_float4(acc[r][0], acc[r][1], acc[r][2], acc[r][3]);
        *reinterpret_cast<float4*>(&g_branch[m * 128 + col0 + 4]) =
            make_float4(acc[r][4], acc[r][5], acc[r][6], acc[r][7]);
    }
}

// ================= prep: geometry + spring + dual compaction =================
__global__ void __launch_bounds__(256)
prep_kernel(const float* __restrict__ init_x,  const float* __restrict__ query_x,
            const float* __restrict__ init_v,  const float* __restrict__ query_v,
            const float* __restrict__ init_av, const float* __restrict__ query_av,
            const float* __restrict__ spring_w0,const float* __restrict__ spring_b0,
            const float* __restrict__ spring_w1,const float* __restrict__ spring_b1,
            float* __restrict__ out) {
    __shared__ float sSw0[128], sSb0[128], sSw1[128];
    const int tid = threadIdx.x;
    if (tid < 128) {
        sSw0[tid] = spring_w0[tid];
        sSb0[tid] = spring_b0[tid];
        sSw1[tid] = spring_w1[tid];
    }
    __syncthreads();

    const int sub = tid >> 6, t = tid & 63;
    const int bo  = blockIdx.x * 4 + sub;
    const int b   = bo >> 6;
    const int gid = bo * 64 + t;

    const float* ip = init_x + (size_t)bo * 9;
    float i0 = ip[0], i1 = ip[1], i2 = ip[2], i3 = ip[3], i4 = ip[4];
    float i7 = ip[7], i8 = ip[8];
    float iv0 = init_v[bo * 2], iv1 = init_v[bo * 2 + 1];
    float iav = init_av[bo];
    const float* qp = query_x + (size_t)(b * 64 + t) * 9;
    float q0 = qp[0], q1 = qp[1], q2 = qp[2], q3 = qp[3], q4 = qp[4];
    float q7 = qp[7], q8 = qp[8];
    float rel0 = q0 - i0, rel1 = q1 - i1;
    float qvx = query_v[(b * 64 + t) * 2]     - iv0;
    float qvy = query_v[(b * 64 + t) * 2 + 1] - iv1;
    float qav = query_av[b * 64 + t] - iav;

    float2 sc1 = g_isc[bo];
    float2 sc2 = g_qsc[b * 64 + t];
    float o1x = i2 * 0.5f * sc1.x, o1y = i2 * 0.5f * sc1.y;
    float ab1x = 2.f * o1x, ab1y = 2.f * o1y;
    float ss1 = ab1x * ab1x + ab1y * ab1y + 1e-8f;
    float o2x = q2 * 0.5f * sc2.x, o2y = q2 * 0.5f * sc2.y;
    float A2x = rel0 - o2x, A2y = rel1 - o2y;
    float B2x = rel0 + o2x, B2y = rel1 + o2y;
    float ab2x = 2.f * o2x, ab2y = 2.f * o2y;
    float ss2 = ab2x * ab2x + ab2y * ab2y + 1e-8f;
    float d = fminf(fminf(ptseg(A2x, A2y, -o1x, -o1y, ab1x, ab1y, ss1),
                          ptseg(B2x, B2y, -o1x, -o1y, ab1x, ab1y, ss1)),
                    fminf(ptseg(-o1x, -o1y, A2x, A2y, ab2x, ab2y, ss2),
                          ptseg( o1x,  o1y, A2x, A2y, ab2x, ab2y, ss2)));
    float dist = d - i4 - q4;
    bool active = (dist <= 0.f);

    float sfx = 0.f, sfy = 0.f;
    if (i8 == q8 && i8 > 0.f) {
        float len = sqrtf(rel0 * rel0 + rel1 * rel1);
        float sf = 0.f;
#pragma unroll 4
        for (int j = 0; j < 128; j++)
            sf = fmaf(fmaxf(fmaf(len, sSw0[j], sSb0[j]), 0.f), sSw1[j], sf);
        sf += __ldg(spring_b1);
        float inv = 1.f / (len + 1e-8f);
        sfx = sf * (-rel0 * inv);
        sfy = sf * (-rel1 * inv);
    }
    float* o = out + (size_t)gid * 3;
    o[0] = sfx; o[1] = sfy; o[2] = 0.f;

    // dist-active compaction
    {
        unsigned bal = __ballot_sync(0xffffffffu, active);
        int rank = __popc(bal & ((1u << (tid & 31)) - 1u));
        int base = 0;
        if ((tid & 31) == 0) base = atomicAdd(&g_nact, __popc(bal));
        base = __shfl_sync(0xffffffffu, base, 0);
        if (active) {
            int slot = base + rank;
            g_cidx[slot] = gid;
            float* cp = g_cin + (size_t)slot * 12;
            cp[0] = rel0; cp[1] = rel1; cp[2] = q2; cp[3] = q3; cp[4] = q4;
            cp[5] = qvx;  cp[6] = qvy;  cp[7] = qav; cp[8] = dist * 100.f;
        }
    }

    // joint-active compaction
    {
        float ti7 = truncf(i7), tq7 = truncf(q7);
        bool hj = (ti7 == tq7 && i7 > 0.f);
        unsigned bal = __ballot_sync(0xffffffffu, hj);
        int rank = __popc(bal & ((1u << (tid & 31)) - 1u));
        int base = 0;
        if ((tid & 31) == 0) base = atomicAdd(&g_njoint, __popc(bal));
        base = __shfl_sync(0xffffffffu, base, 0);
        if (hj) {
            int slot = base + rank;
            g_jidx[slot] = gid;
            float* jn = g_jin + (size_t)slot * 16;
            jn[0] = 0.f;  jn[1] = 0.f;  jn[2] = i2;  jn[3] = i3;  jn[4] = i4;
            jn[5] = rel0; jn[6] = rel1; jn[7] = q2;  jn[8] = q3;  jn[9] = q4;
            jn[10] = qvx; jn[11] = qvy; jn[12] = iav; jn[13] = qav;
            jn[14] = i7 - ti7; jn[15] = 0.f;
        }
    }
}

// ======== joint MLP as tiled GEMM: 64-row tiles, 128 thr, 8x8 micro-tile ========
__global__ void __launch_bounds__(128)
joint_kernel(const float* __restrict__ joint_w0, const float* __restrict__ joint_b0,
             const float* __restrict__ joint_w1, const float* __restrict__ joint_b1,
             float* __restrict__ out) {
    __shared__ __align__(16) float sW0[1920];      // 15 x 128, k-major
    __shared__ __align__(16) float sB0[128];
    __shared__ __align__(16) float sW1[256];
    __shared__ __align__(16) float sJin[64 * 16];
    __shared__ float sB1[2];
    __shared__ __align__(16) int   sJidx[64];

    const int tid = threadIdx.x;
    for (int i = tid; i < 1920; i += 128) sW0[i] = joint_w0[i];
    for (int i = tid; i < 256; i += 128)  sW1[i] = joint_w1[i];
    sB0[tid] = joint_b0[tid];
    if (tid < 2) sB1[tid] = joint_b1[tid];

    const int n = g_njoint;
    const int ntiles = (n + 63) >> 6;

    const int tx = tid & 15, ty = tid >> 4;   // 16 col-groups x 8 row-groups
    const int r0 = ty * 8, c0 = tx * 8;

    for (int tile = blockIdx.x; tile < ntiles; tile += gridDim.x) {
        const int base = tile << 6;
        __syncthreads();   // protect sJin/sJidx reuse across iterations
        for (int i = tid; i < 256; i += 128) {
            int row = i >> 2, p = i & 3;
            float4 v = (base + row < n)
                ? __ldg(reinterpret_cast<const float4*>(g_jin + (size_t)(base + row) * 16) + p)
                : make_float4(0.f, 0.f, 0.f, 0.f);
            reinterpret_cast<float4*>(sJin)[i] = v;
        }
        if (tid < 64) sJidx[tid] = (base + tid < n) ? g_jidx[base + tid] : -1;
        __syncthreads();

        float acc[8][8];
#pragma unroll
        for (int c = 0; c < 8; c++) {
            float bv = sB0[c0 + c];
#pragma unroll
            for (int r = 0; r < 8; r++) acc[r][c] = bv;
        }
#pragma unroll
        for (int k = 0; k < 15; k++) {
            float a[8];
#pragma unroll
            for (int r = 0; r < 8; r++) a[r] = sJin[(r0 + r) * 16 + k];
            float4 t0 = *reinterpret_cast<const float4*>(sW0 + k * 128 + c0);
            float4 t1 = *reinterpret_cast<const float4*>(sW0 + k * 128 + c0 + 4);
            float bv[8] = {t0.x, t0.y, t0.z, t0.w, t1.x, t1.y, t1.z, t1.w};
#pragma unroll
            for (int r = 0; r < 8; r++)
#pragma unroll
                for (int c = 0; c < 8; c++)
                    acc[r][c] = fmaf(a[r], bv[c], acc[r][c]);
        }

        float p[8][2];
#pragma unroll
        for (int r = 0; r < 8; r++) { p[r][0] = 0.f; p[r][1] = 0.f; }
#pragma unroll
        for (int c = 0; c < 8; c++) {
            int j = c0 + c;
            float w1a = sW1[j * 2], w1b = sW1[j * 2 + 1];
#pragma unroll
            for (int r = 0; r < 8; r++) {
                float h = fmaxf(acc[r][c], 0.f);
                p[r][0] = fmaf(h, w1a, p[r][0]);
                p[r][1] = fmaf(h, w1b, p[r][1]);
            }
        }
#pragma unroll
        for (int off = 8; off >= 1; off >>= 1) {
#pragma unroll
            for (int r = 0; r < 8; r++) {
                p[r][0] += __shfl_down_sync(0xffffffffu, p[r][0], off, 16);
                p[r][1] += __shfl_down_sync(0xffffffffu, p[r][1], off, 16);
            }
        }
        if (tx == 0) {
#pragma unroll
            for (int r = 0; r < 8; r++) {
                int idx = sJidx[r0 + r];
                if (idx >= 0) {
                    out[(size_t)idx * 3]     += p[r][0] + sB1[0];
                    out[(size_t)idx * 3 + 1] += p[r][1] + sB1[1];
                }
            }
        }
    }
}

// ==== trunk: 64-row tiles, 256 thr (16 warps/SM), 4x8 micro-tile, dyn queue ====
__global__ void __launch_bounds__(256, 2)
trunk_kernel(const float* __restrict__ trunk_w0, const float* __restrict__ trunk_b0,
             const float* __restrict__ trunk_ws, const float* __restrict__ trunk_bs,
             const float* __restrict__ out_w,    const float* __restrict__ out_b,
             float* __restrict__ out) {
    extern __shared__ float sm[];
    __shared__ int s_tile;
    const int tid = threadIdx.x;

    for (int i = tid; i < 1152; i += 256) sm[T_TW0 + i] = trunk_w0[i];
    if (tid < 128) {
        sm[T_TB0 + tid]  = trunk_b0[tid];
        sm[T_TBS0 + tid] = trunk_bs[tid];
        sm[T_TBS1 + tid] = trunk_bs[128 + tid];
    }
    for (int i = tid; i < 384; i += 256) sm[T_OW + i] = out_w[i];
    if (tid < 3) sm[T_OB + tid] = out_b[tid];

    const int n = g_nact;
    const int ntiles = (n + 63) >> 6;

    const int tx = tid & 15, ty = tid >> 4;   // 16 col-groups x 16 row-groups
    const int r0 = ty * 4, c0 = tx * 8;
    float* sA   = sm + T_A;
    float* sIn  = sm + T_IN;
    int*   sIdx = reinterpret_cast<int*>(sm + T_IDX);

    while (true) {
        __syncthreads();                        // protects s_tile + smem reuse
        if (tid == 0) s_tile = atomicAdd(&g_tile, 1);
        __syncthreads();
        const int tile = s_tile;
        if (tile >= ntiles) break;
        const int base = tile << 6;

        // stage layer-1 weights + tile inputs
        {
            const float4* src = reinterpret_cast<const float4*>(trunk_ws);
            float4* dst = reinterpret_cast<float4*>(sm + T_W);
            for (int i = tid; i < 4096; i += 256) dst[i] = src[i];
        }
        for (int i = tid; i < 192; i += 256) {
            int row = i / 3, p = i % 3;
            float4 v = (base + row < n)
                ? reinterpret_cast<const float4*>(g_cin + (size_t)(base + row) * 12)[p]
                : make_float4(0.f, 0.f, 0.f, 0.f);
            reinterpret_cast<float4*>(sIn)[row * 3 + p] = v;
        }
        if (tid < 64) sIdx[tid] = (base + tid < n) ? g_cidx[base + tid] : -1;
        __syncthreads();

        float acc[4][8];
        // ---- L0: 9 -> 128 ----
        init_acc(sm + T_TB0, c0, acc);
        gemm_small<9, 12>(sIn, sm + T_TW0, r0, c0, acc);
        store_relu(sA, r0, c0, acc);
        __syncthreads();

        // ---- L1: 128 -> 128 (weights = trunk_ws[0] in T_W) ----
        init_acc(sm + T_TBS0, c0, acc);
        gemm128(sA, sm + T_W, r0, c0, acc);
        __syncthreads();
        store_relu(sA, r0, c0, acc);
        {   // reload weights with trunk_ws[1]
            const float4* src = reinterpret_cast<const float4*>(trunk_ws + 16384);
            float4* dst = reinterpret_cast<float4*>(sm + T_W);
            for (int i = tid; i < 4096; i += 256) dst[i] = src[i];
        }
        __syncthreads();

        // ---- L2: 128 -> 128 (no relu) ----
        init_acc(sm + T_TBS1, c0, acc);
        gemm128(sA, sm + T_W, r0, c0, acc);

        // ---- epilogue: (branch ⊙ trunk) @ out_w ----
        float p[4][3];
#pragma unroll
        for (int r = 0; r < 4; r++) { p[r][0] = 0.f; p[r][1] = 0.f; p[r][2] = 0.f; }
#pragma unroll
        for (int r = 0; r < 4; r++) {
            int idx = sIdx[r0 + r];
            int bo = (idx >= 0) ? (idx >> 6) : 0;
            float4 b0 = __ldg(reinterpret_cast<const float4*>(g_branch + bo * 128 + c0));
            float4 b1 = __ldg(reinterpret_cast<const float4*>(g_branch + bo * 128 + c0 + 4));
            float br[8] = {b0.x, b0.y, b0.z, b0.w, b1.x, b1.y, b1.z, b1.w};
#pragma unroll
            for (int c = 0; c < 8; c++) {
                int j = c0 + c;
                float v = br[c] * acc[r][c];
                p[r][0] = fmaf(v, sm[T_OW + j * 3],     p[r][0]);
                p[r][1] = fmaf(v, sm[T_OW + j * 3 + 1], p[r][1]);
                p[r][2] = fmaf(v, sm[T_OW + j * 3 + 2], p[r][2]);
            }
        }
#pragma unroll
        for (int off = 8; off >= 1; off >>= 1) {
#pragma unroll
            for (int r = 0; r < 4; r++) {
                p[r][0] += __shfl_down_sync(0xffffffffu, p[r][0], off, 16);
                p[r][1] += __shfl_down_sync(0xffffffffu, p[r][1], off, 16);
                p[r][2] += __shfl_down_sync(0xffffffffu, p[r][2], off, 16);
            }
        }
        if (tx == 0) {
            float ob0 = sm[T_OB], ob1 = sm[T_OB + 1], ob2 = sm[T_OB + 2];
#pragma unroll
            for (int r = 0; r < 4; r++) {
                int idx = sIdx[r0 + r];
                if (idx >= 0) {
                    float* o = out + (size_t)idx * 3;
                    o[0] += p[r][0] + ob0;
                    o[1] += p[r][1] + ob1;
                    o[2] += p[r][2] + ob2;
                }
            }
        }
    }
}

// ================= launch =================
extern "C" void kernel_launch(void* const* d_in, const int* in_sizes, int n_in,
                              void* d_out, int out_size) {
    const float* init_x    = (const float*)d_in[0];
    const float* query_x   = (const float*)d_in[1];
    const float* init_v    = (const float*)d_in[2];
    const float* query_v   = (const float*)d_in[3];
    const float* init_av   = (const float*)d_in[4];
    const float* query_av  = (const float*)d_in[5];
    const float* trunk_w0  = (const float*)d_in[6];
    const float* trunk_b0  = (const float*)d_in[7];
    const float* trunk_ws  = (const float*)d_in[8];
    const float* trunk_bs  = (const float*)d_in[9];
    const float* branch_w0 = (const float*)d_in[10];
    const float* branch_b0 = (const float*)d_in[11];
    const float* branch_ws = (const float*)d_in[12];
    const float* branch_bs = (const float*)d_in[13];
    const float* out_w     = (const float*)d_in[14];
    const float* out_b     = (const float*)d_in[15];
    const float* spring_w0 = (const float*)d_in[16];
    const float* spring_b0 = (const float*)d_in[17];
    const float* spring_w1 = (const float*)d_in[18];
    const float* spring_b1 = (const float*)d_in[19];
    const float* joint_w0  = (const float*)d_in[20];
    const float* joint_b0  = (const float*)d_in[21];
    const float* joint_w1  = (const float*)d_in[22];
    const float* joint_b1  = (const float*)d_in[23];
    float* out = (float*)d_out;

    cudaFuncSetAttribute(branch_kernel, cudaFuncAttributeMaxDynamicSharedMemorySize,
                         SM_BR_BYTES);
    cudaFuncSetAttribute(trunk_kernel, cudaFuncAttributeMaxDynamicSharedMemorySize,
                         T_BYTES);

    sincos_kernel<<<64, 128>>>(init_x, query_x);
    branch_kernel<<<64, 256, SM_BR_BYTES>>>(init_x, branch_w0, branch_b0,
                                            branch_ws, branch_bs);
    prep_kernel<<<1024, 256>>>(init_x, query_x, init_v, query_v,
                               init_av, query_av,
                               spring_w0, spring_b0, spring_w1, spring_b1, out);
    joint_kernel<<<592, 128>>>(joint_w0, joint_b0, joint_w1, joint_b1, out);
    trunk_kernel<<<296, 256, T_BYTES>>>(trunk_w0, trunk_b0, trunk_ws, trunk_bs,
                                        out_w, out_b, out);
}

// round 15
// speedup vs baseline: 1.2657x; 1.2657x over previous
#include <cuda_runtime.h>
#include <math.h>

#define AS 132  // padded activation row stride (floats)

// ================= global scratch =================
__device__ float  g_branch[4096 * 128];   // branch MLP output per (b,o)
__device__ int    g_nact;                 // dist-active row counter
__device__ int    g_njoint;               // joint-active row counter
__device__ int    g_tile;                 // trunk dynamic tile counter
__device__ int    g_cidx[262144];         // compacted dist-active row index
__device__ float  g_cin[262144 * 12];     // compacted trunk inputs
__device__ int    g_jidx[262144];         // compacted joint row index
__device__ float  g_jin[262144 * 16];     // compacted joint inputs (15 used)
__device__ float2 g_isc[4096];            // (cos,sin) of init angle per (b,o)
__device__ float2 g_qsc[4096];            // (cos,sin) of query angle per (b,t)

// ================= branch kernel layout (256 thr) =================
#define BO_W    0
#define BO_A    16384
#define BO_BW0  (BO_A + 64*AS)
#define BO_BB0  (BO_BW0 + 640)
#define BO_BBS0 (BO_BB0 + 128)
#define BO_BBS1 (BO_BBS0 + 128)
#define BO_IN   (BO_BBS1 + 128)
#define SM_BR_FLOATS (BO_IN + 64*8)
#define SM_BR_BYTES  (SM_BR_FLOATS * 4)

// ==== trunk layout (256 thr, 128-row tile, W0+W1 resident, 1 CTA/SM) ====
#define K2_W0   0
#define K2_W1   16384
#define K2_A    32768                 // 128*AS = 16896
#define K2_TW0  (K2_A + 128*AS)
#define K2_TB0  (K2_TW0 + 1152)
#define K2_TBS0 (K2_TB0 + 128)
#define K2_TBS1 (K2_TBS0 + 128)
#define K2_OW   (K2_TBS1 + 128)
#define K2_OB   (K2_OW + 384)
#define K2_IN   (K2_OB + 4)           // 128*12 = 1536
#define K2_IDX  (K2_IN + 1536)        // 128
#define K2_FLOATS (K2_IDX + 128)
#define K2_BYTES  (K2_FLOATS * 4)     // ~213 KB -> 1 CTA/SM

// ================= helpers =================
__device__ __forceinline__ float ptseg(float px, float py, float ax, float ay,
                                       float abx, float aby, float s) {
    float t = ((px - ax) * abx + (py - ay) * aby) / s;
    t = fminf(fmaxf(t, 0.f), 1.f);
    float dx = px - (ax + t * abx);
    float dy = py - (ay + t * aby);
    return sqrtf(dx * dx + dy * dy);
}

// ---- 4x8 micro-tile GEMM (branch kernel) ----
__device__ __forceinline__ void gemm128(const float* __restrict__ sA,
                                        const float* __restrict__ sW,
                                        int row0, int col0, float acc[4][8]) {
#pragma unroll 2
    for (int k = 0; k < 128; k += 4) {
        float a[4][4];
#pragma unroll
        for (int r = 0; r < 4; r++) {
            float4 t = *reinterpret_cast<const float4*>(sA + (row0 + r) * AS + k);
            a[r][0] = t.x; a[r][1] = t.y; a[r][2] = t.z; a[r][3] = t.w;
        }
#pragma unroll
        for (int kk = 0; kk < 4; kk++) {
            float4 t0 = *reinterpret_cast<const float4*>(sW + (k + kk) * 128 + col0);
            float4 t1 = *reinterpret_cast<const float4*>(sW + (k + kk) * 128 + col0 + 4);
            float bv[8] = {t0.x, t0.y, t0.z, t0.w, t1.x, t1.y, t1.z, t1.w};
#pragma unroll
            for (int r = 0; r < 4; r++)
#pragma unroll
                for (int c = 0; c < 8; c++)
                    acc[r][c] = fmaf(a[r][kk], bv[c], acc[r][c]);
        }
    }
}

template <int K, int STRIDE>
__device__ __forceinline__ void gemm_small(const float* __restrict__ sIn,
                                           const float* __restrict__ sW0,
                                           int row0, int col0, float acc[4][8]) {
#pragma unroll
    for (int k = 0; k < K; k++) {
        float a[4];
#pragma unroll
        for (int r = 0; r < 4; r++) a[r] = sIn[(row0 + r) * STRIDE + k];
        float4 t0 = *reinterpret_cast<const float4*>(sW0 + k * 128 + col0);
        float4 t1 = *reinterpret_cast<const float4*>(sW0 + k * 128 + col0 + 4);
        float bv[8] = {t0.x, t0.y, t0.z, t0.w, t1.x, t1.y, t1.z, t1.w};
#pragma unroll
        for (int r = 0; r < 4; r++)
#pragma unroll
            for (int c = 0; c < 8; c++)
                acc[r][c] = fmaf(a[r], bv[c], acc[r][c]);
    }
}

__device__ __forceinline__ void store_relu(float* sA, int row0, int col0,
                                           const float acc[4][8]) {
#pragma unroll
    for (int r = 0; r < 4; r++) {
        float4 v0 = make_float4(fmaxf(acc[r][0], 0.f), fmaxf(acc[r][1], 0.f),
                                fmaxf(acc[r][2], 0.f), fmaxf(acc[r][3], 0.f));
        float4 v1 = make_float4(fmaxf(acc[r][4], 0.f), fmaxf(acc[r][5], 0.f),
                                fmaxf(acc[r][6], 0.f), fmaxf(acc[r][7], 0.f));
        *reinterpret_cast<float4*>(sA + (row0 + r) * AS + col0)     = v0;
        *reinterpret_cast<float4*>(sA + (row0 + r) * AS + col0 + 4) = v1;
    }
}

__device__ __forceinline__ void init_acc(const float* __restrict__ bias,
                                         int col0, float acc[4][8]) {
#pragma unroll
    for (int c = 0; c < 8; c++) {
        float bv = bias[col0 + c];
#pragma unroll
        for (int r = 0; r < 4; r++) acc[r][c] = bv;
    }
}

// ---- 8x8 micro-tile GEMM (trunk) ----
__device__ __forceinline__ void gemm128_8(const float* __restrict__ sA,
                                          const float* __restrict__ sW,
                                          int r0, int c0, float acc[8][8]) {
#pragma unroll 2
    for (int k = 0; k < 128; k += 4) {
        float a[8][4];
#pragma unroll
        for (int r = 0; r < 8; r++) {
            float4 t = *reinterpret_cast<const float4*>(sA + (r0 + r) * AS + k);
            a[r][0] = t.x; a[r][1] = t.y; a[r][2] = t.z; a[r][3] = t.w;
        }
#pragma unroll
        for (int kk = 0; kk < 4; kk++) {
            float4 t0 = *reinterpret_cast<const float4*>(sW + (k + kk) * 128 + c0);
            float4 t1 = *reinterpret_cast<const float4*>(sW + (k + kk) * 128 + c0 + 4);
            float bv[8] = {t0.x, t0.y, t0.z, t0.w, t1.x, t1.y, t1.z, t1.w};
#pragma unroll
            for (int r = 0; r < 8; r++)
#pragma unroll
                for (int c = 0; c < 8; c++)
                    acc[r][c] = fmaf(a[r][kk], bv[c], acc[r][c]);
        }
    }
}

__device__ __forceinline__ void store_relu8(float* sA, int r0, int c0,
                                            const float acc[8][8]) {
#pragma unroll
    for (int r = 0; r < 8; r++) {
        float4 v0 = make_float4(fmaxf(acc[r][0], 0.f), fmaxf(acc[r][1], 0.f),
                                fmaxf(acc[r][2], 0.f), fmaxf(acc[r][3], 0.f));
        float4 v1 = make_float4(fmaxf(acc[r][4], 0.f), fmaxf(acc[r][5], 0.f),
                                fmaxf(acc[r][6], 0.f), fmaxf(acc[r][7], 0.f));
        *reinterpret_cast<float4*>(sA + (r0 + r) * AS + c0)     = v0;
        *reinterpret_cast<float4*>(sA + (r0 + r) * AS + c0 + 4) = v1;
    }
}

// ================= kernel: sincos dedup + counter zeroing =================
__global__ void __launch_bounds__(128)
sincos_kernel(const float* __restrict__ init_x, const float* __restrict__ query_x) {
    int i = blockIdx.x * 128 + threadIdx.x;
    if (i == 0) { g_nact = 0; g_njoint = 0; g_tile = 0; }
    if (i < 4096) {
        double s, c;
        sincos((double)init_x[(size_t)i * 9 + 3] * 100.0, &s, &c);
        g_isc[i] = make_float2((float)c, (float)s);
    } else if (i < 8192) {
        int q = i - 4096;
        double s, c;
        sincos((double)query_x[(size_t)q * 9 + 3] * 100.0, &s, &c);
        g_qsc[q] = make_float2((float)c, (float)s);
    }
}

// ================= branch prepass (4096 rows) =================
__global__ void __launch_bounds__(256, 1)
branch_kernel(const float* __restrict__ init_x,
              const float* __restrict__ branch_w0, const float* __restrict__ branch_b0,
              const float* __restrict__ branch_ws, const float* __restrict__ branch_bs) {
    extern __shared__ float sm[];
    const int tid = threadIdx.x;
    const int tx = tid & 15, ty = tid >> 4;
    const int row0 = ty * 4, col0 = tx * 8;

    float* sW   = sm + BO_W;
    float* sA   = sm + BO_A;
    float* sBw0 = sm + BO_BW0;
    float* sBb0 = sm + BO_BB0;
    float* sBbs0= sm + BO_BBS0;
    float* sBbs1= sm + BO_BBS1;
    float* sIn  = sm + BO_IN;

    for (int i = tid; i < 640; i += 256) sBw0[i] = branch_w0[i];
    if (tid < 128) {
        sBb0[tid]  = branch_b0[tid];
        sBbs0[tid] = branch_bs[tid];
        sBbs1[tid] = branch_bs[128 + tid];
    }

    if (tid < 64) {
        int bo = blockIdx.x * 64 + tid;
        const float* ip = init_x + (size_t)bo * 9;
        float* in = sIn + tid * 8;
        in[0] = 0.f; in[1] = 0.f; in[2] = ip[2]; in[3] = ip[3]; in[4] = ip[4];
        in[5] = 0.f; in[6] = 0.f; in[7] = 0.f;
    } else {
        const float4* src = reinterpret_cast<const float4*>(branch_ws);
        float4* dst = reinterpret_cast<float4*>(sW);
        for (int i = tid - 64; i < 4096; i += 192) dst[i] = src[i];
    }
    __syncthreads();

    float acc[4][8];
    init_acc(sBb0, col0, acc);
    gemm_small<5, 8>(sIn, sBw0, row0, col0, acc);
    store_relu(sA, row0, col0, acc);
    __syncthreads();

    init_acc(sBbs0, col0, acc);
    gemm128(sA, sW, row0, col0, acc);
    __syncthreads();
    store_relu(sA, row0, col0, acc);
    {
        const float4* src = reinterpret_cast<const float4*>(branch_ws + 128 * 128);
        float4* dst = reinterpret_cast<float4*>(sW);
        for (int i = tid; i < 4096; i += 256) dst[i] = src[i];
    }
    __syncthreads();

    init_acc(sBbs1, col0, acc);
    gemm128(sA, sW, row0, col0, acc);

#pragma unroll
    for (int r = 0; r < 4; r++) {
        int m = blockIdx.x * 64 + row0 + r;
        *reinterpret_cast<float4*>(&g_branch[m * 128 + col0]) =
            make_float4(acc[r][0], acc[r][1], acc[r][2], acc[r][3]);
        *reinterpret_cast<float4*>(&g_branch[m * 128 + col0 + 4]) =
            make_float4(acc[r][4], acc[r][5], acc[r][6], acc[r][7]);
    }
}

// ================= prep: geometry + spring + dual compaction =================
__global__ void __launch_bounds__(256)
prep_kernel(const float* __restrict__ init_x,  const float* __restrict__ query_x,
            const float* __restrict__ init_v,  const float* __restrict__ query_v,
            const float* __restrict__ init_av, const float* __restrict__ query_av,
            const float* __restrict__ spring_w0,const float* __restrict__ spring_b0,
            const float* __restrict__ spring_w1,const float* __restrict__ spring_b1,
            float* __restrict__ out) {
    __shared__ float sSw0[128], sSb0[128], sSw1[128];
    const int tid = threadIdx.x;
    if (tid < 128) {
        sSw0[tid] = spring_w0[tid];
        sSb0[tid] = spring_b0[tid];
        sSw1[tid] = spring_w1[tid];
    }
    __syncthreads();

    const int sub = tid >> 6, t = tid & 63;
    const int bo  = blockIdx.x * 4 + sub;
    const int b   = bo >> 6;
    const int gid = bo * 64 + t;

    const float* ip = init_x + (size_t)bo * 9;
    float i0 = ip[0], i1 = ip[1], i2 = ip[2], i3 = ip[3], i4 = ip[4];
    float i7 = ip[7], i8 = ip[8];
    float iv0 = init_v[bo * 2], iv1 = init_v[bo * 2 + 1];
    float iav = init_av[bo];
    const float* qp = query_x + (size_t)(b * 64 + t) * 9;
    float q0 = qp[0], q1 = qp[1], q2 = qp[2], q3 = qp[3], q4 = qp[4];
    float q7 = qp[7], q8 = qp[8];
    float rel0 = q0 - i0, rel1 = q1 - i1;
    float qvx = query_v[(b * 64 + t) * 2]     - iv0;
    float qvy = query_v[(b * 64 + t) * 2 + 1] - iv1;
    float qav = query_av[b * 64 + t] - iav;

    float2 sc1 = g_isc[bo];
    float2 sc2 = g_qsc[b * 64 + t];
    float o1x = i2 * 0.5f * sc1.x, o1y = i2 * 0.5f * sc1.y;
    float ab1x = 2.f * o1x, ab1y = 2.f * o1y;
    float ss1 = ab1x * ab1x + ab1y * ab1y + 1e-8f;
    float o2x = q2 * 0.5f * sc2.x, o2y = q2 * 0.5f * sc2.y;
    float A2x = rel0 - o2x, A2y = rel1 - o2y;
    float B2x = rel0 + o2x, B2y = rel1 + o2y;
    float ab2x = 2.f * o2x, ab2y = 2.f * o2y;
    float ss2 = ab2x * ab2x + ab2y * ab2y + 1e-8f;
    float d = fminf(fminf(ptseg(A2x, A2y, -o1x, -o1y, ab1x, ab1y, ss1),
                          ptseg(B2x, B2y, -o1x, -o1y, ab1x, ab1y, ss1)),
                    fminf(ptseg(-o1x, -o1y, A2x, A2y, ab2x, ab2y, ss2),
                          ptseg( o1x,  o1y, A2x, A2y, ab2x, ab2y, ss2)));
    float dist = d - i4 - q4;
    bool active = (dist <= 0.f);

    float sfx = 0.f, sfy = 0.f;
    if (i8 == q8 && i8 > 0.f) {
        float len = sqrtf(rel0 * rel0 + rel1 * rel1);
        float sf = 0.f;
#pragma unroll 4
        for (int j = 0; j < 128; j++)
            sf = fmaf(fmaxf(fmaf(len, sSw0[j], sSb0[j]), 0.f), sSw1[j], sf);
        sf += __ldg(spring_b1);
        float inv = 1.f / (len + 1e-8f);
        sfx = sf * (-rel0 * inv);
        sfy = sf * (-rel1 * inv);
    }
    float* o = out + (size_t)gid * 3;
    o[0] = sfx; o[1] = sfy; o[2] = 0.f;

    // dist-active compaction
    {
        unsigned bal = __ballot_sync(0xffffffffu, active);
        int rank = __popc(bal & ((1u << (tid & 31)) - 1u));
        int base = 0;
        if ((tid & 31) == 0) base = atomicAdd(&g_nact, __popc(bal));
        base = __shfl_sync(0xffffffffu, base, 0);
        if (active) {
            int slot = base + rank;
            g_cidx[slot] = gid;
            float* cp = g_cin + (size_t)slot * 12;
            cp[0] = rel0; cp[1] = rel1; cp[2] = q2; cp[3] = q3; cp[4] = q4;
            cp[5] = qvx;  cp[6] = qvy;  cp[7] = qav; cp[8] = dist * 100.f;
        }
    }

    // joint-active compaction
    {
        float ti7 = truncf(i7), tq7 = truncf(q7);
        bool hj = (ti7 == tq7 && i7 > 0.f);
        unsigned bal = __ballot_sync(0xffffffffu, hj);
        int rank = __popc(bal & ((1u << (tid & 31)) - 1u));
        int base = 0;
        if ((tid & 31) == 0) base = atomicAdd(&g_njoint, __popc(bal));
        base = __shfl_sync(0xffffffffu, base, 0);
        if (hj) {
            int slot = base + rank;
            g_jidx[slot] = gid;
            float* jn = g_jin + (size_t)slot * 16;
            jn[0] = 0.f;  jn[1] = 0.f;  jn[2] = i2;  jn[3] = i3;  jn[4] = i4;
            jn[5] = rel0; jn[6] = rel1; jn[7] = q2;  jn[8] = q3;  jn[9] = q4;
            jn[10] = qvx; jn[11] = qvy; jn[12] = iav; jn[13] = qav;
            jn[14] = i7 - ti7; jn[15] = 0.f;
        }
    }
}

// ======== joint MLP as tiled GEMM: 64-row tiles, 128 thr, 8x8 micro-tile ========
__global__ void __launch_bounds__(128)
joint_kernel(const float* __restrict__ joint_w0, const float* __restrict__ joint_b0,
             const float* __restrict__ joint_w1, const float* __restrict__ joint_b1,
             float* __restrict__ out) {
    __shared__ __align__(16) float sW0[1920];      // 15 x 128, k-major
    __shared__ __align__(16) float sB0[128];
    __shared__ __align__(16) float sW1[256];
    __shared__ __align__(16) float sJin[64 * 16];
    __shared__ float sB1[2];
    __shared__ __align__(16) int   sJidx[64];

    const int tid = threadIdx.x;
    for (int i = tid; i < 1920; i += 128) sW0[i] = joint_w0[i];
    for (int i = tid; i < 256; i += 128)  sW1[i] = joint_w1[i];
    sB0[tid] = joint_b0[tid];
    if (tid < 2) sB1[tid] = joint_b1[tid];

    const int n = g_njoint;
    const int ntiles = (n + 63) >> 6;

    const int tx = tid & 15, ty = tid >> 4;   // 16 col-groups x 8 row-groups
    const int r0 = ty * 8, c0 = tx * 8;

    for (int tile = blockIdx.x; tile < ntiles; tile += gridDim.x) {
        const int base = tile << 6;
        __syncthreads();   // protect sJin/sJidx reuse across iterations
        for (int i = tid; i < 256; i += 128) {
            int row = i >> 2, p = i & 3;
            float4 v = (base + row < n)
                ? __ldg(reinterpret_cast<const float4*>(g_jin + (size_t)(base + row) * 16) + p)
                : make_float4(0.f, 0.f, 0.f, 0.f);
            reinterpret_cast<float4*>(sJin)[i] = v;
        }
        if (tid < 64) sJidx[tid] = (base + tid < n) ? g_jidx[base + tid] : -1;
        __syncthreads();

        float acc[8][8];
#pragma unroll
        for (int c = 0; c < 8; c++) {
            float bv = sB0[c0 + c];
#pragma unroll
            for (int r = 0; r < 8; r++) acc[r][c] = bv;
        }
#pragma unroll
        for (int k = 0; k < 15; k++) {
            float a[8];
#pragma unroll
            for (int r = 0; r < 8; r++) a[r] = sJin[(r0 + r) * 16 + k];
            float4 t0 = *reinterpret_cast<const float4*>(sW0 + k * 128 + c0);
            float4 t1 = *reinterpret_cast<const float4*>(sW0 + k * 128 + c0 + 4);
            float bv[8] = {t0.x, t0.y, t0.z, t0.w, t1.x, t1.y, t1.z, t1.w};
#pragma unroll
            for (int r = 0; r < 8; r++)
#pragma unroll
                for (int c = 0; c < 8; c++)
                    acc[r][c] = fmaf(a[r], bv[c], acc[r][c]);
        }

        float p[8][2];
#pragma unroll
        for (int r = 0; r < 8; r++) { p[r][0] = 0.f; p[r][1] = 0.f; }
#pragma unroll
        for (int c = 0; c < 8; c++) {
            int j = c0 + c;
            float w1a = sW1[j * 2], w1b = sW1[j * 2 + 1];
#pragma unroll
            for (int r = 0; r < 8; r++) {
                float h = fmaxf(acc[r][c], 0.f);
                p[r][0] = fmaf(h, w1a, p[r][0]);
                p[r][1] = fmaf(h, w1b, p[r][1]);
            }
        }
#pragma unroll
        for (int off = 8; off >= 1; off >>= 1) {
#pragma unroll
            for (int r = 0; r < 8; r++) {
                p[r][0] += __shfl_down_sync(0xffffffffu, p[r][0], off, 16);
                p[r][1] += __shfl_down_sync(0xffffffffu, p[r][1], off, 16);
            }
        }
        if (tx == 0) {
#pragma unroll
            for (int r = 0; r < 8; r++) {
                int idx = sJidx[r0 + r];
                if (idx >= 0) {
                    out[(size_t)idx * 3]     += p[r][0] + sB1[0];
                    out[(size_t)idx * 3 + 1] += p[r][1] + sB1[1];
                }
            }
        }
    }
}

// ==== trunk: 128-row tiles, 256 thr, 8x8, W0+W1 resident, grid-stride ====
__global__ void __launch_bounds__(256, 1)
trunk_kernel(const float* __restrict__ trunk_w0, const float* __restrict__ trunk_b0,
             const float* __restrict__ trunk_ws, const float* __restrict__ trunk_bs,
             const float* __restrict__ out_w,    const float* __restrict__ out_b,
             float* __restrict__ out) {
    extern __shared__ float sm[];
    const int tid = threadIdx.x;

    {
        const float4* src = reinterpret_cast<const float4*>(trunk_ws);
        float4* dst = reinterpret_cast<float4*>(sm + K2_W0);
        for (int i = tid; i < 8192; i += 256) dst[i] = src[i];
    }
    for (int i = tid; i < 1152; i += 256) sm[K2_TW0 + i] = trunk_w0[i];
    if (tid < 128) {
        sm[K2_TB0 + tid]  = trunk_b0[tid];
        sm[K2_TBS0 + tid] = trunk_bs[tid];
        sm[K2_TBS1 + tid] = trunk_bs[128 + tid];
    }
    for (int i = tid; i < 384; i += 256) sm[K2_OW + i] = out_w[i];
    if (tid < 3) sm[K2_OB + tid] = out_b[tid];

    const int n = g_nact;
    const int ntiles = (n + 127) >> 7;
    __syncthreads();

    const int tx = tid & 15, ty = tid >> 4;
    const int r0 = ty * 8, c0 = tx * 8;
    float* sA  = sm + K2_A;
    float* sIn = sm + K2_IN;
    int*   sIdx = reinterpret_cast<int*>(sm + K2_IDX);

    for (int tile = blockIdx.x; tile < ntiles; tile += gridDim.x) {
        const int base = tile << 7;
        for (int i = tid; i < 384; i += 256) {
            int row = i / 3, p = i % 3;
            float4 v = (base + row < n)
                ? reinterpret_cast<const float4*>(g_cin + (size_t)(base + row) * 12)[p]
                : make_float4(0.f, 0.f, 0.f, 0.f);
            reinterpret_cast<float4*>(sIn)[row * 3 + p] = v;
        }
        for (int i = tid; i < 128; i += 256)
            sIdx[i] = (base + i < n) ? g_cidx[base + i] : -1;
        __syncthreads();

        float acc[8][8];
        // ---- L0: 9 -> 128 ----
#pragma unroll
        for (int c = 0; c < 8; c++) {
            float bv = sm[K2_TB0 + c0 + c];
#pragma unroll
            for (int r = 0; r < 8; r++) acc[r][c] = bv;
        }
#pragma unroll
        for (int k = 0; k < 9; k++) {
            float a[8];
#pragma unroll
            for (int r = 0; r < 8; r++) a[r] = sIn[(r0 + r) * 12 + k];
            float4 t0 = *reinterpret_cast<const float4*>(sm + K2_TW0 + k * 128 + c0);
            float4 t1 = *reinterpret_cast<const float4*>(sm + K2_TW0 + k * 128 + c0 + 4);
            float bv[8] = {t0.x, t0.y, t0.z, t0.w, t1.x, t1.y, t1.z, t1.w};
#pragma unroll
            for (int r = 0; r < 8; r++)
#pragma unroll
                for (int c = 0; c < 8; c++)
                    acc[r][c] = fmaf(a[r], bv[c], acc[r][c]);
        }
        store_relu8(sA, r0, c0, acc);
        __syncthreads();

        // ---- L1: 128 -> 128 ----
#pragma unroll
        for (int c = 0; c < 8; c++) {
            float bv = sm[K2_TBS0 + c0 + c];
#pragma unroll
            for (int r = 0; r < 8; r++) acc[r][c] = bv;
        }
        gemm128_8(sA, sm + K2_W0, r0, c0, acc);
        __syncthreads();
        store_relu8(sA, r0, c0, acc);
        __syncthreads();

        // ---- L2: 128 -> 128 (no relu) ----
#pragma unroll
        for (int c = 0; c < 8; c++) {
            float bv = sm[K2_TBS1 + c0 + c];
#pragma unroll
            for (int r = 0; r < 8; r++) acc[r][c] = bv;
        }
        gemm128_8(sA, sm + K2_W1, r0, c0, acc);

        // ---- epilogue: (branch ⊙ trunk) @ out_w ----
        float p[8][3];
#pragma unroll
        for (int r = 0; r < 8; r++) { p[r][0] = 0.f; p[r][1] = 0.f; p[r][2] = 0.f; }
#pragma unroll
        for (int r = 0; r < 8; r++) {
            int idx = sIdx[r0 + r];
            int bo = (idx >= 0) ? (idx >> 6) : 0;
            float4 b0 = __ldg(reinterpret_cast<const float4*>(g_branch + bo * 128 + c0));
            float4 b1 = __ldg(reinterpret_cast<const float4*>(g_branch + bo * 128 + c0 + 4));
            float br[8] = {b0.x, b0.y, b0.z, b0.w, b1.x, b1.y, b1.z, b1.w};
#pragma unroll
            for (int c = 0; c < 8; c++) {
                int j = c0 + c;
                float v = br[c] * acc[r][c];
                p[r][0] = fmaf(v, sm[K2_OW + j * 3],     p[r][0]);
                p[r][1] = fmaf(v, sm[K2_OW + j * 3 + 1], p[r][1]);
                p[r][2] = fmaf(v, sm[K2_OW + j * 3 + 2], p[r][2]);
            }
        }
#pragma unroll
        for (int off = 8; off >= 1; off >>= 1) {
#pragma unroll
            for (int r = 0; r < 8; r++) {
                p[r][0] += __shfl_down_sync(0xffffffffu, p[r][0], off, 16);
                p[r][1] += __shfl_down_sync(0xffffffffu, p[r][1], off, 16);
                p[r][2] += __shfl_down_sync(0xffffffffu, p[r][2], off, 16);
            }
        }
        if (tx == 0) {
            float ob0 = sm[K2_OB], ob1 = sm[K2_OB + 1], ob2 = sm[K2_OB + 2];
#pragma unroll
            for (int r = 0; r < 8; r++) {
                int idx = sIdx[r0 + r];
                if (idx >= 0) {
                    float* o = out + (size_t)idx * 3;
                    o[0] += p[r][0] + ob0;
                    o[1] += p[r][1] + ob1;
                    o[2] += p[r][2] + ob2;
                }
            }
        }
        __syncthreads();
    }
}

// ================= launch =================
extern "C" void kernel_launch(void* const* d_in, const int* in_sizes, int n_in,
                              void* d_out, int out_size) {
    const float* init_x    = (const float*)d_in[0];
    const float* query_x   = (const float*)d_in[1];
    const float* init_v    = (const float*)d_in[2];
    const float* query_v   = (const float*)d_in[3];
    const float* init_av   = (const float*)d_in[4];
    const float* query_av  = (const float*)d_in[5];
    const float* trunk_w0  = (const float*)d_in[6];
    const float* trunk_b0  = (const float*)d_in[7];
    const float* trunk_ws  = (const float*)d_in[8];
    const float* trunk_bs  = (const float*)d_in[9];
    const float* branch_w0 = (const float*)d_in[10];
    const float* branch_b0 = (const float*)d_in[11];
    const float* branch_ws = (const float*)d_in[12];
    const float* branch_bs = (const float*)d_in[13];
    const float* out_w     = (const float*)d_in[14];
    const float* out_b     = (const float*)d_in[15];
    const float* spring_w0 = (const float*)d_in[16];
    const float* spring_b0 = (const float*)d_in[17];
    const float* spring_w1 = (const float*)d_in[18];
    const float* spring_b1 = (const float*)d_in[19];
    const float* joint_w0  = (const float*)d_in[20];
    const float* joint_b0  = (const float*)d_in[21];
    const float* joint_w1  = (const float*)d_in[22];
    const float* joint_b1  = (const float*)d_in[23];
    float* out = (float*)d_out;

    cudaFuncSetAttribute(branch_kernel, cudaFuncAttributeMaxDynamicSharedMemorySize,
                         SM_BR_BYTES);
    cudaFuncSetAttribute(trunk_kernel, cudaFuncAttributeMaxDynamicSharedMemorySize,
                         K2_BYTES);

    sincos_kernel<<<64, 128>>>(init_x, query_x);
    branch_kernel<<<64, 256, SM_BR_BYTES>>>(init_x, branch_w0, branch_b0,
                                            branch_ws, branch_bs);
    prep_kernel<<<1024, 256>>>(init_x, query_x, init_v, query_v,
                               init_av, query_av,
                               spring_w0, spring_b0, spring_w1, spring_b1, out);
    joint_kernel<<<592, 128>>>(joint_w0, joint_b0, joint_w1, joint_b1, out);
    trunk_kernel<<<148, 256, K2_BYTES>>>(trunk_w0, trunk_b0, trunk_ws, trunk_bs,
                                         out_w, out_b, out);
}

// round 16
// speedup vs baseline: 1.4145x; 1.1176x over previous
#include <cuda_runtime.h>
#include <math.h>

#define AS 132  // padded activation row stride (floats)

// ================= global scratch =================
__device__ float  g_branch[4096 * 128];   // branch MLP output per (b,o)
__device__ int    g_nact;                 // dist-active row counter
__device__ int    g_njoint;               // joint-active row counter
__device__ int    g_tile;                 // (unused; kept for layout stability)
__device__ int    g_cidx[262144];         // compacted dist-active row index
__device__ float  g_cin[262144 * 12];     // compacted trunk inputs
__device__ int    g_jidx[262144];         // compacted joint row index
__device__ float  g_jin[262144 * 16];     // compacted joint inputs (15 used)
__device__ float2 g_isc[4096];            // (cos,sin) of init angle per (b,o)
__device__ float2 g_qsc[4096];            // (cos,sin) of query angle per (b,t)

// ================= branch kernel layout (256 thr) =================
#define BO_W    0
#define BO_A    16384
#define BO_BW0  (BO_A + 64*AS)
#define BO_BB0  (BO_BW0 + 640)
#define BO_BBS0 (BO_BB0 + 128)
#define BO_BBS1 (BO_BBS0 + 128)
#define BO_IN   (BO_BBS1 + 128)
#define SM_BR_FLOATS (BO_IN + 64*8)
#define SM_BR_BYTES  (SM_BR_FLOATS * 4)

// ==== fused trunk+joint layout (256 thr, 128-row tiles, 1 CTA/SM) ====
#define K2_W0   0
#define K2_W1   16384
#define K2_A    32768                 // 128*AS = 16896 (also joint jin staging)
#define K2_TW0  (K2_A + 128*AS)
#define K2_TB0  (K2_TW0 + 1152)
#define K2_TBS0 (K2_TB0 + 128)
#define K2_TBS1 (K2_TBS0 + 128)
#define K2_OW   (K2_TBS1 + 128)
#define K2_OB   (K2_OW + 384)
#define K2_IN   (K2_OB + 4)           // 128*12 = 1536
#define K2_IDX  (K2_IN + 1536)        // 128
#define K2_JW0  (K2_IDX + 128)        // 15x128 = 1920
#define K2_JB0  (K2_JW0 + 1920)       // 128
#define K2_JW1  (K2_JB0 + 128)        // 256
#define K2_JB1  (K2_JW1 + 256)        // 2 (+2 pad)
#define K2_FLOATS (K2_JB1 + 4)
#define K2_BYTES  (K2_FLOATS * 4)     // ~222 KB -> 1 CTA/SM

// ================= helpers =================
__device__ __forceinline__ float ptseg(float px, float py, float ax, float ay,
                                       float abx, float aby, float s) {
    float t = ((px - ax) * abx + (py - ay) * aby) / s;
    t = fminf(fmaxf(t, 0.f), 1.f);
    float dx = px - (ax + t * abx);
    float dy = py - (ay + t * aby);
    return sqrtf(dx * dx + dy * dy);
}

// ---- 4x8 micro-tile GEMM (branch kernel) ----
__device__ __forceinline__ void gemm128(const float* __restrict__ sA,
                                        const float* __restrict__ sW,
                                        int row0, int col0, float acc[4][8]) {
#pragma unroll 2
    for (int k = 0; k < 128; k += 4) {
        float a[4][4];
#pragma unroll
        for (int r = 0; r < 4; r++) {
            float4 t = *reinterpret_cast<const float4*>(sA + (row0 + r) * AS + k);
            a[r][0] = t.x; a[r][1] = t.y; a[r][2] = t.z; a[r][3] = t.w;
        }
#pragma unroll
        for (int kk = 0; kk < 4; kk++) {
            float4 t0 = *reinterpret_cast<const float4*>(sW + (k + kk) * 128 + col0);
            float4 t1 = *reinterpret_cast<const float4*>(sW + (k + kk) * 128 + col0 + 4);
            float bv[8] = {t0.x, t0.y, t0.z, t0.w, t1.x, t1.y, t1.z, t1.w};
#pragma unroll
            for (int r = 0; r < 4; r++)
#pragma unroll
                for (int c = 0; c < 8; c++)
                    acc[r][c] = fmaf(a[r][kk], bv[c], acc[r][c]);
        }
    }
}

template <int K, int STRIDE>
__device__ __forceinline__ void gemm_small(const float* __restrict__ sIn,
                                           const float* __restrict__ sW0,
                                           int row0, int col0, float acc[4][8]) {
#pragma unroll
    for (int k = 0; k < K; k++) {
        float a[4];
#pragma unroll
        for (int r = 0; r < 4; r++) a[r] = sIn[(row0 + r) * STRIDE + k];
        float4 t0 = *reinterpret_cast<const float4*>(sW0 + k * 128 + col0);
        float4 t1 = *reinterpret_cast<const float4*>(sW0 + k * 128 + col0 + 4);
        float bv[8] = {t0.x, t0.y, t0.z, t0.w, t1.x, t1.y, t1.z, t1.w};
#pragma unroll
        for (int r = 0; r < 4; r++)
#pragma unroll
            for (int c = 0; c < 8; c++)
                acc[r][c] = fmaf(a[r], bv[c], acc[r][c]);
    }
}

__device__ __forceinline__ void store_relu(float* sA, int row0, int col0,
                                           const float acc[4][8]) {
#pragma unroll
    for (int r = 0; r < 4; r++) {
        float4 v0 = make_float4(fmaxf(acc[r][0], 0.f), fmaxf(acc[r][1], 0.f),
                                fmaxf(acc[r][2], 0.f), fmaxf(acc[r][3], 0.f));
        float4 v1 = make_float4(fmaxf(acc[r][4], 0.f), fmaxf(acc[r][5], 0.f),
                                fmaxf(acc[r][6], 0.f), fmaxf(acc[r][7], 0.f));
        *reinterpret_cast<float4*>(sA + (row0 + r) * AS + col0)     = v0;
        *reinterpret_cast<float4*>(sA + (row0 + r) * AS + col0 + 4) = v1;
    }
}

__device__ __forceinline__ void init_acc(const float* __restrict__ bias,
                                         int col0, float acc[4][8]) {
#pragma unroll
    for (int c = 0; c < 8; c++) {
        float bv = bias[col0 + c];
#pragma unroll
        for (int r = 0; r < 4; r++) acc[r][c] = bv;
    }
}

// ---- 8x8 micro-tile GEMM ----
__device__ __forceinline__ void gemm128_8(const float* __restrict__ sA,
                                          const float* __restrict__ sW,
                                          int r0, int c0, float acc[8][8]) {
#pragma unroll 2
    for (int k = 0; k < 128; k += 4) {
        float a[8][4];
#pragma unroll
        for (int r = 0; r < 8; r++) {
            float4 t = *reinterpret_cast<const float4*>(sA + (r0 + r) * AS + k);
            a[r][0] = t.x; a[r][1] = t.y; a[r][2] = t.z; a[r][3] = t.w;
        }
#pragma unroll
        for (int kk = 0; kk < 4; kk++) {
            float4 t0 = *reinterpret_cast<const float4*>(sW + (k + kk) * 128 + c0);
            float4 t1 = *reinterpret_cast<const float4*>(sW + (k + kk) * 128 + c0 + 4);
            float bv[8] = {t0.x, t0.y, t0.z, t0.w, t1.x, t1.y, t1.z, t1.w};
#pragma unroll
            for (int r = 0; r < 8; r++)
#pragma unroll
                for (int c = 0; c < 8; c++)
                    acc[r][c] = fmaf(a[r][kk], bv[c], acc[r][c]);
        }
    }
}

__device__ __forceinline__ void store_relu8(float* sA, int r0, int c0,
                                            const float acc[8][8]) {
#pragma unroll
    for (int r = 0; r < 8; r++) {
        float4 v0 = make_float4(fmaxf(acc[r][0], 0.f), fmaxf(acc[r][1], 0.f),
                                fmaxf(acc[r][2], 0.f), fmaxf(acc[r][3], 0.f));
        float4 v1 = make_float4(fmaxf(acc[r][4], 0.f), fmaxf(acc[r][5], 0.f),
                                fmaxf(acc[r][6], 0.f), fmaxf(acc[r][7], 0.f));
        *reinterpret_cast<float4*>(sA + (r0 + r) * AS + c0)     = v0;
        *reinterpret_cast<float4*>(sA + (r0 + r) * AS + c0 + 4) = v1;
    }
}

// ================= kernel: sincos dedup + counter zeroing =================
__global__ void __launch_bounds__(128)
sincos_kernel(const float* __restrict__ init_x, const float* __restrict__ query_x) {
    int i = blockIdx.x * 128 + threadIdx.x;
    if (i == 0) { g_nact = 0; g_njoint = 0; g_tile = 0; }
    if (i < 4096) {
        double s, c;
        sincos((double)init_x[(size_t)i * 9 + 3] * 100.0, &s, &c);
        g_isc[i] = make_float2((float)c, (float)s);
    } else if (i < 8192) {
        int q = i - 4096;
        double s, c;
        sincos((double)query_x[(size_t)q * 9 + 3] * 100.0, &s, &c);
        g_qsc[q] = make_float2((float)c, (float)s);
    }
}

// ================= branch prepass (4096 rows) =================
__global__ void __launch_bounds__(256, 1)
branch_kernel(const float* __restrict__ init_x,
              const float* __restrict__ branch_w0, const float* __restrict__ branch_b0,
              const float* __restrict__ branch_ws, const float* __restrict__ branch_bs) {
    extern __shared__ float sm[];
    const int tid = threadIdx.x;
    const int tx = tid & 15, ty = tid >> 4;
    const int row0 = ty * 4, col0 = tx * 8;

    float* sW   = sm + BO_W;
    float* sA   = sm + BO_A;
    float* sBw0 = sm + BO_BW0;
    float* sBb0 = sm + BO_BB0;
    float* sBbs0= sm + BO_BBS0;
    float* sBbs1= sm + BO_BBS1;
    float* sIn  = sm + BO_IN;

    for (int i = tid; i < 640; i += 256) sBw0[i] = branch_w0[i];
    if (tid < 128) {
        sBb0[tid]  = branch_b0[tid];
        sBbs0[tid] = branch_bs[tid];
        sBbs1[tid] = branch_bs[128 + tid];
    }

    if (tid < 64) {
        int bo = blockIdx.x * 64 + tid;
        const float* ip = init_x + (size_t)bo * 9;
        float* in = sIn + tid * 8;
        in[0] = 0.f; in[1] = 0.f; in[2] = ip[2]; in[3] = ip[3]; in[4] = ip[4];
        in[5] = 0.f; in[6] = 0.f; in[7] = 0.f;
    } else {
        const float4* src = reinterpret_cast<const float4*>(branch_ws);
        float4* dst = reinterpret_cast<float4*>(sW);
        for (int i = tid - 64; i < 4096; i += 192) dst[i] = src[i];
    }
    __syncthreads();

    float acc[4][8];
    init_acc(sBb0, col0, acc);
    gemm_small<5, 8>(sIn, sBw0, row0, col0, acc);
    store_relu(sA, row0, col0, acc);
    __syncthreads();

    init_acc(sBbs0, col0, acc);
    gemm128(sA, sW, row0, col0, acc);
    __syncthreads();
    store_relu(sA, row0, col0, acc);
    {
        const float4* src = reinterpret_cast<const float4*>(branch_ws + 128 * 128);
        float4* dst = reinterpret_cast<float4*>(sW);
        for (int i = tid; i < 4096; i += 256) dst[i] = src[i];
    }
    __syncthreads();

    init_acc(sBbs1, col0, acc);
    gemm128(sA, sW, row0, col0, acc);

#pragma unroll
    for (int r = 0; r < 4; r++) {
        int m = blockIdx.x * 64 + row0 + r;
        *reinterpret_cast<float4*>(&g_branch[m * 128 + col0]) =
            make_float4(acc[r][0], acc[r][1], acc[r][2], acc[r][3]);
        *reinterpret_cast<float4*>(&g_branch[m * 128 + col0 + 4]) =
            make_float4(acc[r][4], acc[r][5], acc[r][6], acc[r][7]);
    }
}

// ================= prep: geometry + spring + dual compaction =================
__global__ void __launch_bounds__(256)
prep_kernel(const float* __restrict__ init_x,  const float* __restrict__ query_x,
            const float* __restrict__ init_v,  const float* __restrict__ query_v,
            const float* __restrict__ init_av, const float* __restrict__ query_av,
            const float* __restrict__ spring_w0,const float* __restrict__ spring_b0,
            const float* __restrict__ spring_w1,const float* __restrict__ spring_b1,
            float* __restrict__ out) {
    __shared__ float sSw0[128], sSb0[128], sSw1[128];
    const int tid = threadIdx.x;
    if (tid < 128) {
        sSw0[tid] = spring_w0[tid];
        sSb0[tid] = spring_b0[tid];
        sSw1[tid] = spring_w1[tid];
    }
    __syncthreads();

    const int sub = tid >> 6, t = tid & 63;
    const int bo  = blockIdx.x * 4 + sub;
    const int b   = bo >> 6;
    const int gid = bo * 64 + t;

    const float* ip = init_x + (size_t)bo * 9;
    float i0 = ip[0], i1 = ip[1], i2 = ip[2], i3 = ip[3], i4 = ip[4];
    float i7 = ip[7], i8 = ip[8];
    float iv0 = init_v[bo * 2], iv1 = init_v[bo * 2 + 1];
    float iav = init_av[bo];
    const float* qp = query_x + (size_t)(b * 64 + t) * 9;
    float q0 = qp[0], q1 = qp[1], q2 = qp[2], q3 = qp[3], q4 = qp[4];
    float q7 = qp[7], q8 = qp[8];
    float rel0 = q0 - i0, rel1 = q1 - i1;
    float qvx = query_v[(b * 64 + t) * 2]     - iv0;
    float qvy = query_v[(b * 64 + t) * 2 + 1] - iv1;
    float qav = query_av[b * 64 + t] - iav;

    float2 sc1 = g_isc[bo];
    float2 sc2 = g_qsc[b * 64 + t];
    float o1x = i2 * 0.5f * sc1.x, o1y = i2 * 0.5f * sc1.y;
    float ab1x = 2.f * o1x, ab1y = 2.f * o1y;
    float ss1 = ab1x * ab1x + ab1y * ab1y + 1e-8f;
    float o2x = q2 * 0.5f * sc2.x, o2y = q2 * 0.5f * sc2.y;
    float A2x = rel0 - o2x, A2y = rel1 - o2y;
    float B2x = rel0 + o2x, B2y = rel1 + o2y;
    float ab2x = 2.f * o2x, ab2y = 2.f * o2y;
    float ss2 = ab2x * ab2x + ab2y * ab2y + 1e-8f;
    float d = fminf(fminf(ptseg(A2x, A2y, -o1x, -o1y, ab1x, ab1y, ss1),
                          ptseg(B2x, B2y, -o1x, -o1y, ab1x, ab1y, ss1)),
                    fminf(ptseg(-o1x, -o1y, A2x, A2y, ab2x, ab2y, ss2),
                          ptseg( o1x,  o1y, A2x, A2y, ab2x, ab2y, ss2)));
    float dist = d - i4 - q4;
    bool active = (dist <= 0.f);

    float sfx = 0.f, sfy = 0.f;
    if (i8 == q8 && i8 > 0.f) {
        float len = sqrtf(rel0 * rel0 + rel1 * rel1);
        float sf = 0.f;
#pragma unroll 4
        for (int j = 0; j < 128; j++)
            sf = fmaf(fmaxf(fmaf(len, sSw0[j], sSb0[j]), 0.f), sSw1[j], sf);
        sf += __ldg(spring_b1);
        float inv = 1.f / (len + 1e-8f);
        sfx = sf * (-rel0 * inv);
        sfy = sf * (-rel1 * inv);
    }
    float* o = out + (size_t)gid * 3;
    o[0] = sfx; o[1] = sfy; o[2] = 0.f;

    // dist-active compaction
    {
        unsigned bal = __ballot_sync(0xffffffffu, active);
        int rank = __popc(bal & ((1u << (tid & 31)) - 1u));
        int base = 0;
        if ((tid & 31) == 0) base = atomicAdd(&g_nact, __popc(bal));
        base = __shfl_sync(0xffffffffu, base, 0);
        if (active) {
            int slot = base + rank;
            g_cidx[slot] = gid;
            float* cp = g_cin + (size_t)slot * 12;
            cp[0] = rel0; cp[1] = rel1; cp[2] = q2; cp[3] = q3; cp[4] = q4;
            cp[5] = qvx;  cp[6] = qvy;  cp[7] = qav; cp[8] = dist * 100.f;
        }
    }

    // joint-active compaction
    {
        float ti7 = truncf(i7), tq7 = truncf(q7);
        bool hj = (ti7 == tq7 && i7 > 0.f);
        unsigned bal = __ballot_sync(0xffffffffu, hj);
        int rank = __popc(bal & ((1u << (tid & 31)) - 1u));
        int base = 0;
        if ((tid & 31) == 0) base = atomicAdd(&g_njoint, __popc(bal));
        base = __shfl_sync(0xffffffffu, base, 0);
        if (hj) {
            int slot = base + rank;
            g_jidx[slot] = gid;
            float* jn = g_jin + (size_t)slot * 16;
            jn[0] = 0.f;  jn[1] = 0.f;  jn[2] = i2;  jn[3] = i3;  jn[4] = i4;
            jn[5] = rel0; jn[6] = rel1; jn[7] = q2;  jn[8] = q3;  jn[9] = q4;
            jn[10] = qvx; jn[11] = qvy; jn[12] = iav; jn[13] = qav;
            jn[14] = i7 - ti7; jn[15] = 0.f;
        }
    }
}

// ==== fused trunk+joint: 128-row tiles, 256 thr, 8x8, weights resident ====
__global__ void __launch_bounds__(256, 1)
trunk_kernel(const float* __restrict__ trunk_w0, const float* __restrict__ trunk_b0,
             const float* __restrict__ trunk_ws, const float* __restrict__ trunk_bs,
             const float* __restrict__ out_w,    const float* __restrict__ out_b,
             const float* __restrict__ joint_w0, const float* __restrict__ joint_b0,
             const float* __restrict__ joint_w1, const float* __restrict__ joint_b1,
             float* __restrict__ out) {
    extern __shared__ float sm[];
    const int tid = threadIdx.x;

    {
        const float4* src = reinterpret_cast<const float4*>(trunk_ws);
        float4* dst = reinterpret_cast<float4*>(sm + K2_W0);
        for (int i = tid; i < 8192; i += 256) dst[i] = src[i];
    }
    for (int i = tid; i < 1152; i += 256) sm[K2_TW0 + i] = trunk_w0[i];
    for (int i = tid; i < 1920; i += 256) sm[K2_JW0 + i] = joint_w0[i];
    if (tid < 128) {
        sm[K2_TB0 + tid]  = trunk_b0[tid];
        sm[K2_TBS0 + tid] = trunk_bs[tid];
        sm[K2_TBS1 + tid] = trunk_bs[128 + tid];
        sm[K2_JB0 + tid]  = joint_b0[tid];
    }
    for (int i = tid; i < 384; i += 256) sm[K2_OW + i] = out_w[i];
    sm[K2_JW1 + tid] = joint_w1[tid];
    if (tid < 3) sm[K2_OB + tid] = out_b[tid];
    if (tid < 2) sm[K2_JB1 + tid] = joint_b1[tid];

    const int n  = g_nact;
    const int nj = g_njoint;
    const int ntiles = (n + 127) >> 7;
    const int jtiles = (nj + 127) >> 7;
    __syncthreads();

    const int tx = tid & 15, ty = tid >> 4;
    const int r0 = ty * 8, c0 = tx * 8;
    float* sA  = sm + K2_A;
    float* sIn = sm + K2_IN;
    int*   sIdx = reinterpret_cast<int*>(sm + K2_IDX);

    // ================= phase 1: trunk tiles =================
    for (int tile = blockIdx.x; tile < ntiles; tile += gridDim.x) {
        const int base = tile << 7;
        for (int i = tid; i < 384; i += 256) {
            int row = i / 3, p = i % 3;
            float4 v = (base + row < n)
                ? reinterpret_cast<const float4*>(g_cin + (size_t)(base + row) * 12)[p]
                : make_float4(0.f, 0.f, 0.f, 0.f);
            reinterpret_cast<float4*>(sIn)[row * 3 + p] = v;
        }
        for (int i = tid; i < 128; i += 256)
            sIdx[i] = (base + i < n) ? g_cidx[base + i] : -1;
        __syncthreads();

        float acc[8][8];
        // ---- L0: 9 -> 128 ----
#pragma unroll
        for (int c = 0; c < 8; c++) {
            float bv = sm[K2_TB0 + c0 + c];
#pragma unroll
            for (int r = 0; r < 8; r++) acc[r][c] = bv;
        }
#pragma unroll
        for (int k = 0; k < 9; k++) {
            float a[8];
#pragma unroll
            for (int r = 0; r < 8; r++) a[r] = sIn[(r0 + r) * 12 + k];
            float4 t0 = *reinterpret_cast<const float4*>(sm + K2_TW0 + k * 128 + c0);
            float4 t1 = *reinterpret_cast<const float4*>(sm + K2_TW0 + k * 128 + c0 + 4);
            float bv[8] = {t0.x, t0.y, t0.z, t0.w, t1.x, t1.y, t1.z, t1.w};
#pragma unroll
            for (int r = 0; r < 8; r++)
#pragma unroll
                for (int c = 0; c < 8; c++)
                    acc[r][c] = fmaf(a[r], bv[c], acc[r][c]);
        }
        store_relu8(sA, r0, c0, acc);
        __syncthreads();

        // ---- L1: 128 -> 128 ----
#pragma unroll
        for (int c = 0; c < 8; c++) {
            float bv = sm[K2_TBS0 + c0 + c];
#pragma unroll
            for (int r = 0; r < 8; r++) acc[r][c] = bv;
        }
        gemm128_8(sA, sm + K2_W0, r0, c0, acc);
        __syncthreads();
        store_relu8(sA, r0, c0, acc);
        __syncthreads();

        // ---- L2: 128 -> 128 (no relu) ----
#pragma unroll
        for (int c = 0; c < 8; c++) {
            float bv = sm[K2_TBS1 + c0 + c];
#pragma unroll
            for (int r = 0; r < 8; r++) acc[r][c] = bv;
        }
        gemm128_8(sA, sm + K2_W1, r0, c0, acc);

        // ---- epilogue: (branch ⊙ trunk) @ out_w ----
        float p[8][3];
#pragma unroll
        for (int r = 0; r < 8; r++) { p[r][0] = 0.f; p[r][1] = 0.f; p[r][2] = 0.f; }
#pragma unroll
        for (int r = 0; r < 8; r++) {
            int idx = sIdx[r0 + r];
            int bo = (idx >= 0) ? (idx >> 6) : 0;
            float4 b0 = __ldg(reinterpret_cast<const float4*>(g_branch + bo * 128 + c0));
            float4 b1 = __ldg(reinterpret_cast<const float4*>(g_branch + bo * 128 + c0 + 4));
            float br[8] = {b0.x, b0.y, b0.z, b0.w, b1.x, b1.y, b1.z, b1.w};
#pragma unroll
            for (int c = 0; c < 8; c++) {
                int j = c0 + c;
                float v = br[c] * acc[r][c];
                p[r][0] = fmaf(v, sm[K2_OW + j * 3],     p[r][0]);
                p[r][1] = fmaf(v, sm[K2_OW + j * 3 + 1], p[r][1]);
                p[r][2] = fmaf(v, sm[K2_OW + j * 3 + 2], p[r][2]);
            }
        }
#pragma unroll
        for (int off = 8; off >= 1; off >>= 1) {
#pragma unroll
            for (int r = 0; r < 8; r++) {
                p[r][0] += __shfl_down_sync(0xffffffffu, p[r][0], off, 16);
                p[r][1] += __shfl_down_sync(0xffffffffu, p[r][1], off, 16);
                p[r][2] += __shfl_down_sync(0xffffffffu, p[r][2], off, 16);
            }
        }
        if (tx == 0) {
            float ob0 = sm[K2_OB], ob1 = sm[K2_OB + 1], ob2 = sm[K2_OB + 2];
#pragma unroll
            for (int r = 0; r < 8; r++) {
                int idx = sIdx[r0 + r];
                if (idx >= 0) {
                    float* o = out + (size_t)idx * 3;
                    atomicAdd(o,     p[r][0] + ob0);
                    atomicAdd(o + 1, p[r][1] + ob1);
                    atomicAdd(o + 2, p[r][2] + ob2);
                }
            }
        }
        __syncthreads();
    }

    // ================= phase 2: joint tiles (reuse sA as jin staging) =================
    for (int tile = blockIdx.x; tile < jtiles; tile += gridDim.x) {
        const int base = tile << 7;
        __syncthreads();
        for (int i = tid; i < 512; i += 256) {
            int row = i >> 2, pq = i & 3;
            float4 v = (base + row < nj)
                ? __ldg(reinterpret_cast<const float4*>(g_jin + (size_t)(base + row) * 16) + pq)
                : make_float4(0.f, 0.f, 0.f, 0.f);
            reinterpret_cast<float4*>(sA)[i] = v;   // stride 16 floats per row
        }
        for (int i = tid; i < 128; i += 256)
            sIdx[i] = (base + i < nj) ? g_jidx[base + i] : -1;
        __syncthreads();

        // L0: [128x15] @ [15x128] + b0
        float acc[8][8];
#pragma unroll
        for (int c = 0; c < 8; c++) {
            float bv = sm[K2_JB0 + c0 + c];
#pragma unroll
            for (int r = 0; r < 8; r++) acc[r][c] = bv;
        }
#pragma unroll
        for (int k = 0; k < 15; k++) {
            float a[8];
#pragma unroll
            for (int r = 0; r < 8; r++) a[r] = sA[(r0 + r) * 16 + k];
            float4 t0 = *reinterpret_cast<const float4*>(sm + K2_JW0 + k * 128 + c0);
            float4 t1 = *reinterpret_cast<const float4*>(sm + K2_JW0 + k * 128 + c0 + 4);
            float bv[8] = {t0.x, t0.y, t0.z, t0.w, t1.x, t1.y, t1.z, t1.w};
#pragma unroll
            for (int r = 0; r < 8; r++)
#pragma unroll
                for (int c = 0; c < 8; c++)
                    acc[r][c] = fmaf(a[r], bv[c], acc[r][c]);
        }

        // L1: relu(acc) @ W1 (128->2)
        float p[8][2];
#pragma unroll
        for (int r = 0; r < 8; r++) { p[r][0] = 0.f; p[r][1] = 0.f; }
#pragma unroll
        for (int c = 0; c < 8; c++) {
            int j = c0 + c;
            float w1a = sm[K2_JW1 + j * 2], w1b = sm[K2_JW1 + j * 2 + 1];
#pragma unroll
            for (int r = 0; r < 8; r++) {
                float h = fmaxf(acc[r][c], 0.f);
                p[r][0] = fmaf(h, w1a, p[r][0]);
                p[r][1] = fmaf(h, w1b, p[r][1]);
            }
        }
#pragma unroll
        for (int off = 8; off >= 1; off >>= 1) {
#pragma unroll
            for (int r = 0; r < 8; r++) {
                p[r][0] += __shfl_down_sync(0xffffffffu, p[r][0], off, 16);
                p[r][1] += __shfl_down_sync(0xffffffffu, p[r][1], off, 16);
            }
        }
        if (tx == 0) {
            float jb0 = sm[K2_JB1], jb1 = sm[K2_JB1 + 1];
#pragma unroll
            for (int r = 0; r < 8; r++) {
                int idx = sIdx[r0 + r];
                if (idx >= 0) {
                    atomicAdd(out + (size_t)idx * 3,     p[r][0] + jb0);
                    atomicAdd(out + (size_t)idx * 3 + 1, p[r][1] + jb1);
                }
            }
        }
    }
}

// ================= launch =================
extern "C" void kernel_launch(void* const* d_in, const int* in_sizes, int n_in,
                              void* d_out, int out_size) {
    const float* init_x    = (const float*)d_in[0];
    const float* query_x   = (const float*)d_in[1];
    const float* init_v    = (const float*)d_in[2];
    const float* query_v   = (const float*)d_in[3];
    const float* init_av   = (const float*)d_in[4];
    const float* query_av  = (const float*)d_in[5];
    const float* trunk_w0  = (const float*)d_in[6];
    const float* trunk_b0  = (const float*)d_in[7];
    const float* trunk_ws  = (const float*)d_in[8];
    const float* trunk_bs  = (const float*)d_in[9];
    const float* branch_w0 = (const float*)d_in[10];
    const float* branch_b0 = (const float*)d_in[11];
    const float* branch_ws = (const float*)d_in[12];
    const float* branch_bs = (const float*)d_in[13];
    const float* out_w     = (const float*)d_in[14];
    const float* out_b     = (const float*)d_in[15];
    const float* spring_w0 = (const float*)d_in[16];
    const float* spring_b0 = (const float*)d_in[17];
    const float* spring_w1 = (const float*)d_in[18];
    const float* spring_b1 = (const float*)d_in[19];
    const float* joint_w0  = (const float*)d_in[20];
    const float* joint_b0  = (const float*)d_in[21];
    const float* joint_w1  = (const float*)d_in[22];
    const float* joint_b1  = (const float*)d_in[23];
    float* out = (float*)d_out;

    cudaFuncSetAttribute(branch_kernel, cudaFuncAttributeMaxDynamicSharedMemorySize,
                         SM_BR_BYTES);
    cudaFuncSetAttribute(trunk_kernel, cudaFuncAttributeMaxDynamicSharedMemorySize,
                         K2_BYTES);

    sincos_kernel<<<64, 128>>>(init_x, query_x);
    branch_kernel<<<64, 256, SM_BR_BYTES>>>(init_x, branch_w0, branch_b0,
                                            branch_ws, branch_bs);
    prep_kernel<<<1024, 256>>>(init_x, query_x, init_v, query_v,
                               init_av, query_av,
                               spring_w0, spring_b0, spring_w1, spring_b1, out);
    trunk_kernel<<<148, 256, K2_BYTES>>>(trunk_w0, trunk_b0, trunk_ws, trunk_bs,
                                         out_w, out_b,
                                         joint_w0, joint_b0, joint_w1, joint_b1, out);
}